// round 17
// baseline (speedup 1.0000x reference)
#include <cuda_runtime.h>

#define NB 32
#define NQ 1024
#define NG 64
#define NT 128           // threads per solver CTA
#define KPT 8            // columns per thread
#define BIGF 3.0e38f

// 8 MB scratch: transposed cost cost[b][i][j], i = gt row, j = proposal col
__device__ float g_cost[NB * NG * NQ];

// ---------------------------------------------------------------------------
// Cost build (exact IEEE order, no FMA contraction -> bit-matches reference fp32)
// ---------------------------------------------------------------------------
__global__ void build_cost_kernel(const float* __restrict__ obj,
                                  const float* __restrict__ cd,
                                  const float* __restrict__ gi) {
    int t = blockIdx.x * blockDim.x + threadIdx.x;
    if (t >= NB * NG * NQ) return;
    int j = t & (NQ - 1);
    int i = (t >> 10) & (NG - 1);
    int b = t >> 16;
    float o = obj[b * NQ + j];
    int src = (b * NQ + j) * NG + i;
    float a0 = __fmul_rn(5.0f, -o);
    float a1 = __fmul_rn(10.0f, cd[src]);
    float a2 = __fmul_rn(2.0f, -gi[src]);
    g_cost[t] = __fadd_rn(__fadd_rn(a0, a1), a2);
}

// Order-preserving u32 key for a float (monotone increasing), exact round-trip.
__device__ __forceinline__ unsigned int flip32(float x) {
    unsigned int b = __float_as_uint(x);
    return (b & 0x80000000u) ? ~b : (b | 0x80000000u);
}
__device__ __forceinline__ float unflip32(unsigned int k) {
    unsigned int b = (k & 0x80000000u) ? (k & 0x7fffffffu) : ~k;
    return __uint_as_float(b);
}
// 49-bit key: [flip32(val):32][idx:10][abit:1][row:6]. Bits below idx are a
// deterministic function of idx within a Dijkstra (row4col static), so they
// never affect the (val, idx) order; ties go to the smaller idx (numpy rule).
__device__ __forceinline__ unsigned long long packkey(float x, int idx,
                                                      unsigned abit, unsigned row) {
    return ((unsigned long long)flip32(x) << 17) |
           ((unsigned long long)idx << 7) |
           ((unsigned long long)abit << 6) | (unsigned long long)row;
}

// thread's k-th column: [4t .. 4t+3] and [512+4t .. 512+4t+3]; inverse k = ((j>>9)<<2)|(j&3)
__device__ __forceinline__ int jcol(int tid, int k) {
    return ((k & 4) << 7) + (tid << 2) + (k & 3);
}

// ---------------------------------------------------------------------------
// Jonker-Volgenant shortest-augmenting-path LSA, one CTA per batch. Pure fp32
// (R13/R14-verified). Per-step chain shortened: the argmin key carries
// {val, idx, assigned, row4col}, and s_scal[j] = shortest[j] - u[row4col[j]]
// is owner-maintained, so after the combine the next cost row LDG issues
// immediately and the scal LDS proceeds in parallel. ONE barrier per step.
// ---------------------------------------------------------------------------
__global__ void __launch_bounds__(NT, 1)
solve_kernel(const int* __restrict__ ngt, float* __restrict__ out) {
    const int b = blockIdx.x;
    const int tid = threadIdx.x;
    const int w = tid >> 5;

    __shared__ float s_short[NQ];            // shortest (for dual updates)
    __shared__ float s_scal[NQ];             // shortest[j] - u[row4col[j]]
    __shared__ uint2 s_colinfo[NQ];          // {u_of_row bits, row} per column
    __shared__ unsigned char s_path[NQ];
    __shared__ float s_u[NG];
    __shared__ short s_col4row[NG];
    __shared__ unsigned char s_inSR[NG];
    __shared__ __align__(16) unsigned long long s_pack[4][4];   // [ring][warp]

    float* outi = out + b * NQ;              // per_prop_gt_inds (as float)
    float* outm = out + NB * NQ + b * NQ;    // proposal_matched_mask

    for (int j = tid; j < NQ; j += NT) { outi[j] = 0.0f; outm[j] = 0.0f; }

    const int g = ngt[b];
    if (g <= 0) return;

    const float* __restrict__ cost = g_cost + b * NG * NQ;

    float v_reg[KPT], sh_reg[KPT];
    unsigned char row_reg[KPT];              // row bits cached for rescan keys
#pragma unroll
    for (int k = 0; k < KPT; ++k) { v_reg[k] = 0.0f; row_reg[k] = 0; }
    unsigned amask = 0;                      // assigned bits for my 8 columns

    for (int i = tid; i < g; i += NT) { s_u[i] = 0.0f; s_col4row[i] = -1; }
    if (tid < 16) s_pack[tid >> 2][tid & 3] = ~0ULL;

    int t = 0;   // ring phase, continuous across Dijkstras
    __syncthreads();

    for (int cur = 0; cur < g; ++cur) {
        unsigned scmask = 0;
        float lbest = BIGF;
        int lidx = 0;
        unsigned labit = 0, lrow = 0;
#pragma unroll
        for (int k = 0; k < KPT; ++k) sh_reg[k] = BIGF;
        for (int i = tid; i < g; i += NT) s_inSR[i] = (i == cur) ? 1 : 0;
        __syncthreads();

        int i = cur;
        float scal = 0.0f;                   // mv - u[i]; 0 for the fresh row
        int sink;
        unsigned long long pfin;

        // ---- Dijkstra over columns: ONE barrier per step ----
        while (true) {
            const float* __restrict__ crow = cost + i * NQ;

            // 2x coalesced LDG.128 covering my 8 columns
            const float4 f0 = *(const float4*)(crow + (tid << 2));
            const float4 f1 = *(const float4*)(crow + 512 + (tid << 2));
            const float cf[KPT] = {f0.x, f0.y, f0.z, f0.w, f1.x, f1.y, f1.z, f1.w};

#pragma unroll
            for (int k = 0; k < KPT; ++k) {
                if (!((scmask >> k) & 1u)) {
                    const float r = (scal + cf[k]) - v_reg[k];
                    if (r < sh_reg[k]) {
                        const int j = jcol(tid, k);
                        sh_reg[k] = r;
                        s_short[j] = r;
                        s_path[j] = (unsigned char)i;
                        if ((amask >> k) & 1u) {          // assigned: maintain scal
                            const uint2 ci = s_colinfo[j];
                            s_scal[j] = r - __uint_as_float(ci.x);
                            row_reg[k] = (unsigned char)ci.y;
                        }
                        if (r < lbest) {
                            lbest = r; lidx = j;
                            labit = (amask >> k) & 1u;
                            lrow = row_reg[k];
                        }
                    }
                }
            }
            if (lbest < BIGF)
                atomicMin(&s_pack[t & 3][w], packkey(lbest, lidx, labit, lrow));
            __syncthreads();

            // all threads combine the 4 per-warp cells
            const unsigned long long* cell = s_pack[t & 3];
            unsigned long long p  = cell[0];
            unsigned long long q1 = cell[1];
            unsigned long long q2 = cell[2];
            unsigned long long q3 = cell[3];
            if (q1 < p) p = q1;
            if (q2 < p) p = q2;
            if (q3 < p) p = q3;
            const int bidx = (int)((p >> 7) & 1023ULL);
            const unsigned abit = (unsigned)((p >> 6) & 1ULL);

            if (tid < 4) s_pack[(t + 2) & 3][tid] = ~0ULL;   // barrier-ordered reset

            // owner removes the visited column and rescans its registers
            if (((bidx & 511) >> 2) == tid) {
                const int kk = ((bidx >> 9) << 2) | (bidx & 3);
                scmask |= 1u << kk;
                lbest = BIGF; lidx = 0; labit = 0; lrow = 0;
#pragma unroll
                for (int k = 0; k < KPT; ++k) {
                    if (!((scmask >> k) & 1u) && sh_reg[k] < lbest) {
                        lbest = sh_reg[k];
                        lidx = jcol(tid, k);
                        labit = (amask >> k) & 1u;
                        lrow = row_reg[k];
                    }
                }
            }
            ++t;
            if (!abit) { sink = bidx; pfin = p; break; }     // unassigned -> done

            i = (int)(p & 63ULL);                // next row: pure ALU from key
            scal = s_scal[bidx];                 // parallel LDS, off the LDG path
            if (tid == 0) s_inSR[i] = 1;
        }

        const float mv = unflip32((unsigned int)(pfin >> 17));  // off-chain, once

        // ---- dual updates (pre-augment col4row) ----
#pragma unroll
        for (int k = 0; k < KPT; ++k) {
            if ((scmask >> k) & 1u) v_reg[k] -= (mv - sh_reg[k]);
        }
        for (int ii = tid; ii < g; ii += NT) {
            if (ii == cur) {
                s_u[ii] += mv;
            } else if (s_inSR[ii]) {
                const int cj = s_col4row[ii];
                const float un = s_u[ii] + (mv - s_short[cj]);
                s_u[ii] = un;
                s_colinfo[cj] = make_uint2(__float_as_uint(un), (unsigned)ii);
            }
        }
        __syncthreads();

        // ---- augment alternating path (serial, short) ----
        if (tid == 0) {
            int j = sink;
            while (true) {
                const int ii = s_path[j];
                s_colinfo[j] = make_uint2(__float_as_uint(s_u[ii]), (unsigned)ii);
                const short nj = s_col4row[ii];
                s_col4row[ii] = (short)j;
                j = nj;
                if (ii == cur) break;
            }
        }
        // sink's owner marks it assigned (uniform: every thread knows sink)
        if (((sink & 511) >> 2) == tid) amask |= 1u << (((sink >> 9) << 2) | (sink & 3));
        __syncthreads();
    }

    // outputs: proposal p = col4row[i] gets index i, mask 1
    for (int i = tid; i < g; i += NT) {
        const int p = s_col4row[i];
        outi[p] = (float)i;
        outm[p] = 1.0f;
    }
}

extern "C" void kernel_launch(void* const* d_in, const int* in_sizes, int n_in,
                              void* d_out, int out_size) {
    const float* obj = (const float*)d_in[1];
    const float* cd  = (const float*)d_in[2];
    const float* gi  = (const float*)d_in[3];
    const int* ngt   = (const int*)d_in[4];
    float* out = (float*)d_out;

    const int total = NB * NG * NQ;
    build_cost_kernel<<<(total + 255) / 256, 256>>>(obj, cd, gi);
    solve_kernel<<<NB, NT>>>(ngt, out);
}